// round 5
// baseline (speedup 1.0000x reference)
#include <cuda_runtime.h>
#include <cuda_bf16.h>
#include <cstdint>

#define SIZE   4096
#define NDOWN  256
#define NT     16
#define MAXB   4096
#define MTILE  128
#define KSPLIT 8
#define KCHUNK (SIZE / KSPLIT)   // 512
#define KTILE  32

// ---------------- device scratch ----------------
__device__ int   g_offsets[NT + 1];
__device__ int   g_sorted[MAXB];
__device__ int   g_rowtask[MAXB];
__device__ int   g_work_t[MAXB / MTILE + NT];
__device__ int   g_work_m0[MAXB / MTILE + NT];
__device__ int   g_nwork;
__device__ float g_part[KSPLIT][MAXB][NDOWN];          // split-K partials
__device__ __align__(16) __nv_bfloat16 g_act[(size_t)MAXB * NDOWN];
__device__ __align__(16) __nv_bfloat16 g_wu[(size_t)NT * NDOWN * SIZE];  // bf16 Wu

// ---------------- helpers ----------------
__device__ __forceinline__ uint32_t smem_u32(const void* p) {
    return (uint32_t)__cvta_generic_to_shared(p);
}
__device__ __forceinline__ void cp_async16(uint32_t dst, const void* src) {
    asm volatile("cp.async.cg.shared.global [%0], [%1], 16;\n"
                 :: "r"(dst), "l"(src) : "memory");
}
__device__ __forceinline__ void cp_commit() {
    asm volatile("cp.async.commit_group;\n" ::: "memory");
}
__device__ __forceinline__ void cp_wait2() {
    asm volatile("cp.async.wait_group 2;\n" ::: "memory");
}
__device__ __forceinline__ uint32_t pack_bf16(float lo, float hi) {
    uint32_t r;
    asm("cvt.rn.bf16x2.f32 %0, %1, %2;" : "=r"(r) : "f"(hi), "f"(lo));
    return r;
}
__device__ __forceinline__ uint4 cvt_f4x2(float4 a, float4 b) {
    uint4 u;
    u.x = pack_bf16(a.x, a.y); u.y = pack_bf16(a.z, a.w);
    u.z = pack_bf16(b.x, b.y); u.w = pack_bf16(b.z, b.w);
    return u;
}
__device__ __forceinline__ void ldsm4(uint32_t& r0, uint32_t& r1, uint32_t& r2, uint32_t& r3,
                                      uint32_t addr) {
    asm volatile("ldmatrix.sync.aligned.m8n8.x4.shared.b16 {%0,%1,%2,%3}, [%4];"
                 : "=r"(r0), "=r"(r1), "=r"(r2), "=r"(r3) : "r"(addr));
}
__device__ __forceinline__ void ldsm4t(uint32_t& r0, uint32_t& r1, uint32_t& r2, uint32_t& r3,
                                       uint32_t addr) {
    asm volatile("ldmatrix.sync.aligned.m8n8.x4.trans.shared.b16 {%0,%1,%2,%3}, [%4];"
                 : "=r"(r0), "=r"(r1), "=r"(r2), "=r"(r3) : "r"(addr));
}
__device__ __forceinline__ void mma_bf16(float& c0, float& c1, float& c2, float& c3,
                                         uint32_t a0, uint32_t a1, uint32_t a2, uint32_t a3,
                                         uint32_t b0, uint32_t b1) {
    asm volatile(
        "mma.sync.aligned.m16n8k16.row.col.f32.bf16.bf16.f32 "
        "{%0,%1,%2,%3}, {%4,%5,%6,%7}, {%8,%9}, {%0,%1,%2,%3};\n"
        : "+f"(c0), "+f"(c1), "+f"(c2), "+f"(c3)
        : "r"(a0), "r"(a1), "r"(a2), "r"(a3), "r"(b0), "r"(b1));
}

// warp-tile compute: 32(M) x 64(N) x 32(K), bf16 via ldmatrix
template <int AST, int BST>
__device__ __forceinline__ void compute_tile(uint32_t aSlot, int aCol, uint32_t bSlot,
                                             int lane, int wm, int wn,
                                             float c[2][8][4]) {
#pragma unroll
    for (int ks = 0; ks < 2; ++ks) {
        uint32_t a[2][4];
#pragma unroll
        for (int mi = 0; mi < 2; mi++) {
            uint32_t addr = aSlot + 2u * ((wm * 32 + mi * 16 + (lane & 15)) * AST
                                          + aCol + ks * 16 + (lane >> 4) * 8);
            ldsm4(a[mi][0], a[mi][1], a[mi][2], a[mi][3], addr);
        }
        uint32_t b[8][2];
#pragma unroll
        for (int nb = 0; nb < 4; nb++) {
            uint32_t addr = bSlot + 2u * ((ks * 16 + ((lane >> 3) & 1) * 8 + (lane & 7)) * BST
                                          + wn * 64 + nb * 16 + (lane >> 4) * 8);
            ldsm4t(b[2 * nb][0], b[2 * nb][1], b[2 * nb + 1][0], b[2 * nb + 1][1], addr);
        }
#pragma unroll
        for (int mi = 0; mi < 2; mi++)
#pragma unroll
            for (int ni = 0; ni < 8; ni++)
                mma_bf16(c[mi][ni][0], c[mi][ni][1], c[mi][ni][2], c[mi][ni][3],
                         a[mi][0], a[mi][1], a[mi][2], a[mi][3],
                         b[ni][0], b[ni][1]);
    }
}

// ---------------- phase A: counting sort + worklist ----------------
__global__ void prep_kernel(const int* __restrict__ task_id, int B) {
    __shared__ int cnt[NT];
    __shared__ int off[NT + 1];
    __shared__ int cur[NT];
    int tid = threadIdx.x;
    if (tid < NT) cnt[tid] = 0;
    __syncthreads();
    for (int i = tid; i < B; i += blockDim.x)
        atomicAdd(&cnt[task_id[i]], 1);
    __syncthreads();
    if (tid == 0) {
        int s = 0, nw = 0;
        for (int t = 0; t < NT; t++) {
            off[t] = s;
            for (int m = s; m < s + cnt[t]; m += MTILE) {
                g_work_t[nw] = t; g_work_m0[nw] = m; nw++;
            }
            s += cnt[t];
        }
        off[NT] = s;
        g_nwork = nw;
    }
    __syncthreads();
    if (tid <= NT) g_offsets[tid] = off[tid];
    if (tid < NT)  cur[tid] = off[tid];
    __syncthreads();
    for (int i = tid; i < B; i += blockDim.x) {
        int t = task_id[i];
        int p = atomicAdd(&cur[t], 1);
        g_sorted[p]  = i;
        g_rowtask[p] = t;
    }
}

// ---------------- phase B: down-proj split-K (bf16 mma), unchanged R4 --------
#define D_AST 40
#define D_BST 264
#define D_SMEM (2 * (MTILE * D_AST + 32 * D_BST) * 2)

__global__ void __launch_bounds__(512, 1) down_kernel(const float* __restrict__ x,
                                                      const float* __restrict__ Wd) {
    if ((int)blockIdx.y >= g_nwork) return;
    const int t    = g_work_t[blockIdx.y];
    const int m0   = g_work_m0[blockIdx.y];
    const int rows = min(MTILE, g_offsets[t + 1] - m0);
    const int ks0  = blockIdx.x * KCHUNK;

    extern __shared__ __align__(16) char smem[];
    __shared__ int s_idx[MTILE];

    const int tid = threadIdx.x;
    if (tid < MTILE) s_idx[tid] = (tid < rows) ? g_sorted[m0 + tid] : -1;
    __syncthreads();

    const uint32_t aU = smem_u32(smem);
    const uint32_t bU = aU + 2u * 2 * MTILE * D_AST;
    const float*   wsrc = Wd + (size_t)t * SIZE * NDOWN;

    const int ar = tid >> 2,   ac = (tid & 3) * 8;
    const int bk = tid >> 4,   bn = (tid & 15) * 16;
    const int aidx = s_idx[ar];
    const float* asrc = x + (size_t)(aidx < 0 ? 0 : aidx) * SIZE + ac;
    const float* bsrc = wsrc + (size_t)bk * NDOWN + bn;

    float4 ra[2], rb[4];
    auto loadA = [&](int j) {
        const float* p = asrc + ks0 + j * KTILE;
        ra[0] = *(const float4*)(p);
        ra[1] = *(const float4*)(p + 4);
    };
    auto loadB = [&](int j) {
        const float* p = bsrc + (size_t)(ks0 + j * KTILE) * NDOWN;
        rb[0] = *(const float4*)(p);
        rb[1] = *(const float4*)(p + 4);
        rb[2] = *(const float4*)(p + 8);
        rb[3] = *(const float4*)(p + 12);
    };
    auto store = [&](int s) {
        *(uint4*)(smem + 2u * ((uint32_t)s * MTILE * D_AST + ar * D_AST + ac)) =
            cvt_f4x2(ra[0], ra[1]);
        char* bbase = smem + 2u * 2 * MTILE * D_AST;
        *(uint4*)(bbase + 2u * ((uint32_t)s * 32 * D_BST + bk * D_BST + bn)) =
            cvt_f4x2(rb[0], rb[1]);
        *(uint4*)(bbase + 2u * ((uint32_t)s * 32 * D_BST + bk * D_BST + bn + 8)) =
            cvt_f4x2(rb[2], rb[3]);
    };

    float c[2][8][4] = {};
    const int lane = tid & 31, wid = tid >> 5;
    const int wm = wid >> 2, wn = wid & 3;

    const int NIT = KCHUNK / KTILE;   // 16
    loadA(0); loadB(0);
    store(0);
    loadA(1); loadB(1);
    __syncthreads();

    for (int it = 0; it < NIT; ++it) {
        const int buf = it & 1;
        compute_tile<D_AST, D_BST>(aU + 2u * (uint32_t)buf * MTILE * D_AST, 0,
                                   bU + 2u * (uint32_t)buf * 32 * D_BST,
                                   lane, wm, wn, c);
        if (it + 1 < NIT) store((it + 1) & 1);
        if (it + 2 < NIT) { loadA(it + 2); loadB(it + 2); }
        __syncthreads();
    }

    const int g = lane >> 2, tg = lane & 3;
    float* pbase = &g_part[blockIdx.x][0][0];
#pragma unroll
    for (int mi = 0; mi < 2; mi++) {
        int r0 = wm * 32 + mi * 16 + g;
        int r1 = r0 + 8;
#pragma unroll
        for (int ni = 0; ni < 8; ni++) {
            int col = wn * 64 + ni * 8 + tg * 2;
            if (r0 < rows)
                *(float2*)(pbase + (size_t)(m0 + r0) * NDOWN + col) =
                    make_float2(c[mi][ni][0], c[mi][ni][1]);
            if (r1 < rows)
                *(float2*)(pbase + (size_t)(m0 + r1) * NDOWN + col) =
                    make_float2(c[mi][ni][2], c[mi][ni][3]);
        }
    }
}

// ------ phase B2: reduce partials + silu -> bf16  AND  convert Wu -> bf16 ----
#define CONV_BLOCKS 2048
__global__ void __launch_bounds__(1024) reduce_convert_kernel(const float* __restrict__ bd,
                                                              const float* __restrict__ Wu,
                                                              int B, int redBlocks) {
    const int bid = blockIdx.x;
    const int tid = threadIdx.x;
    if (bid < redBlocks) {
        int gidx = bid * 1024 + tid;
        if (gidx >= B * NDOWN) return;
        int pos = gidx >> 8;
        int col = gidx & (NDOWN - 1);
        float s = 0.f;
#pragma unroll
        for (int k = 0; k < KSPLIT; k++)
            s += g_part[k][pos][col];
        s += bd[g_rowtask[pos] * NDOWN + col];
        g_act[gidx] = __float2bfloat16(s / (1.f + __expf(-s)));
    } else {
        // convert 16*256*4096 floats = 4,194,304 float4, 2 per thread
        const int cid = (bid - redBlocks) * 1024 + tid;
        const float4* src = (const float4*)Wu;
        uint2*        dst = (uint2*)g_wu;
#pragma unroll
        for (int i = 0; i < 2; i++) {
            int e = cid + i * (CONV_BLOCKS * 1024);
            float4 v = src[e];
            dst[e] = make_uint2(pack_bf16(v.x, v.y), pack_bf16(v.z, v.w));
        }
    }
}

// ---------------- phase C: up-proj, A-resident + 4 N-tiles per CTA -----------
// 256 thr = 8 warps (4x2 of 32x64). A: full [128][256] bf16 in smem (one load).
// B: 4-slot cp.async bf16 pipeline from g_wu, fill distance 2, 1 barrier/iter.
#define U_AST 264   // 256 + 8
#define U_BST 136   // 128 + 8
#define U_NTILES 4
#define U_A_BYTES (MTILE * U_AST * 2)
#define U_SMEM (U_A_BYTES + 4 * 32 * U_BST * 2)   // 67584 + 34816 = 102400

__global__ void __launch_bounds__(256) up_kernel(const float* __restrict__ x,
                                                 const float* __restrict__ bu,
                                                 float* __restrict__ out) {
    if ((int)blockIdx.y >= g_nwork) return;
    const int t     = g_work_t[blockIdx.y];
    const int m0    = g_work_m0[blockIdx.y];
    const int rows  = min(MTILE, g_offsets[t + 1] - m0);
    const int nbase = blockIdx.x * (U_NTILES * 128);

    extern __shared__ __align__(16) char smem[];
    __shared__ int s_orig[MTILE];

    const int tid = threadIdx.x;
    if (tid < MTILE) s_orig[tid] = (tid < rows) ? g_sorted[m0 + tid] : 0;

    const uint32_t aU = smem_u32(smem);
    const uint32_t bU = aU + U_A_BYTES;

    // A: 128x256 bf16 = 4096 x 16B chunks, 16 per thread
    {
        const __nv_bfloat16* asrc = g_act + (size_t)m0 * NDOWN;
#pragma unroll
        for (int i = 0; i < 16; i++) {
            int f = tid + i * 256;
            int r = f >> 5, seg = (f & 31) * 8;
            cp_async16(aU + 2u * ((uint32_t)r * U_AST + seg),
                       asrc + (size_t)r * NDOWN + seg);
        }
        cp_commit();
    }

    // B stage fill: stage = 32(k) x 128(n) bf16 = 512 x 16B chunks, 2 per thread
    const __nv_bfloat16* wbase = g_wu + (size_t)t * NDOWN * SIZE + nbase;
    auto fillB = [&](int j) {
        const int nt = j >> 3, kk = j & 7, slot = j & 3;
#pragma unroll
        for (int i = 0; i < 2; i++) {
            int f = tid + i * 256;
            int kr = f >> 4, seg = (f & 15) * 8;
            cp_async16(bU + 2u * ((uint32_t)slot * 32 * U_BST + kr * U_BST + seg),
                       wbase + (size_t)(kk * 32 + kr) * SIZE + nt * 128 + seg);
        }
        cp_commit();
    };

    float c[2][8][4] = {};
    const int lane = tid & 31, wid = tid >> 5;
    const int wm = wid >> 1, wn = wid & 1;
    const int g = lane >> 2, tg = lane & 3;

    fillB(0);
    fillB(1);

    const int NJ = U_NTILES * 8;   // 32
    for (int j = 0; j < NJ; ++j) {
        if (j + 2 < NJ) fillB(j + 2);
        else            cp_commit();           // keep group count uniform
        cp_wait2();
        __syncthreads();

        const int nt = j >> 3, kk = j & 7;
        compute_tile<U_AST, U_BST>(aU, kk * 32,
                                   bU + 2u * (uint32_t)(j & 3) * 32 * U_BST,
                                   lane, wm, wn, c);

        if (kk == 7) {   // epilogue for this n-tile
            const int n0 = nbase + nt * 128;
            const float* bup = bu + (size_t)t * SIZE + n0;
#pragma unroll
            for (int mi = 0; mi < 2; mi++) {
                int r0 = wm * 32 + mi * 16 + g;
                int r1 = r0 + 8;
#pragma unroll
                for (int ni = 0; ni < 8; ni++) {
                    int col = wn * 64 + ni * 8 + tg * 2;
                    float b0 = bup[col], b1 = bup[col + 1];
                    if (r0 < rows) {
                        size_t o = (size_t)s_orig[r0] * SIZE + n0 + col;
                        out[o]     = x[o]     + c[mi][ni][0] + b0;
                        out[o + 1] = x[o + 1] + c[mi][ni][1] + b1;
                        c[mi][ni][0] = 0.f; c[mi][ni][1] = 0.f;
                    }
                    if (r1 < rows) {
                        size_t o = (size_t)s_orig[r1] * SIZE + n0 + col;
                        out[o]     = x[o]     + c[mi][ni][2] + b0;
                        out[o + 1] = x[o + 1] + c[mi][ni][3] + b1;
                        c[mi][ni][2] = 0.f; c[mi][ni][3] = 0.f;
                    }
                }
            }
            // rows that were masked never accumulate into output; still reset
#pragma unroll
            for (int mi = 0; mi < 2; mi++)
#pragma unroll
                for (int ni = 0; ni < 8; ni++)
#pragma unroll
                    for (int q = 0; q < 4; q++) c[mi][ni][q] = 0.f;
        }
    }
}

// ---------------- launch ----------------
extern "C" void kernel_launch(void* const* d_in, const int* in_sizes, int n_in,
                              void* d_out, int out_size) {
    const float* x       = (const float*)d_in[0];
    const int*   task_id = (const int*)d_in[1];
    const float* Wd      = (const float*)d_in[2];
    const float* bd      = (const float*)d_in[3];
    const float* Wu      = (const float*)d_in[4];
    const float* bu      = (const float*)d_in[5];
    float*       out     = (float*)d_out;
    const int B = in_sizes[1];

    prep_kernel<<<1, 1024>>>(task_id, B);

    cudaFuncSetAttribute(down_kernel, cudaFuncAttributeMaxDynamicSharedMemorySize, D_SMEM);
    cudaFuncSetAttribute(up_kernel,   cudaFuncAttributeMaxDynamicSharedMemorySize, U_SMEM);

    const int maxWork = B / MTILE + NT;
    dim3 gD(KSPLIT, maxWork);
    down_kernel<<<gD, 512, D_SMEM>>>(x, Wd);

    const int redBlocks = (B * NDOWN + 1023) / 1024;
    reduce_convert_kernel<<<redBlocks + CONV_BLOCKS, 1024>>>(bd, Wu, B, redBlocks);

    dim3 gU(SIZE / (U_NTILES * 128), maxWork);   // (8, ...)
    up_kernel<<<gU, 256, U_SMEM>>>(x, bu, out);
}

// round 7
// speedup vs baseline: 1.3530x; 1.3530x over previous
#include <cuda_runtime.h>
#include <cuda_bf16.h>
#include <cstdint>

#define SIZE   4096
#define NDOWN  256
#define NT     16
#define MAXB   4096
#define MTILE  128
#define KSPLIT 8
#define KCHUNK (SIZE / KSPLIT)   // 512
#define KTILE  32

#define AST 40    // A smem stride (bf16): 80B rows, ldmatrix conflict-free
#define BST 136   // B smem stride (bf16): 272B rows, ldmatrix.trans conflict-free

// smem layout (per CTA)
#define A_STAGE   (MTILE * AST * 2)             // 10240
#define BF32_OFF  (3 * A_STAGE)                 // 30720
#define BF32_STAGE (KTILE * 128 * 4)            // 16384
#define BB16_OFF  (BF32_OFF + 3 * BF32_STAGE)   // 79872
#define BB16_STAGE (KTILE * BST * 2)            // 8704
#define SMEM_DYN  (BB16_OFF + 3 * BB16_STAGE)   // 105984

// ---------------- device scratch ----------------
__device__ int   g_offsets[NT + 1];
__device__ int   g_sorted[MAXB];
__device__ int   g_rowtask[MAXB];
__device__ int   g_work_t[MAXB / MTILE + NT];
__device__ int   g_work_m0[MAXB / MTILE + NT];
__device__ int   g_nwork;
__device__ float g_part[KSPLIT][MAXB][NDOWN];
__device__ __align__(16) __nv_bfloat16 g_act[(size_t)MAXB * NDOWN];
__device__ __align__(16) __nv_bfloat16 g_xs[(size_t)MAXB * SIZE];   // bf16 copy of x

// ---------------- helpers ----------------
__device__ __forceinline__ uint32_t smem_u32(const void* p) {
    return (uint32_t)__cvta_generic_to_shared(p);
}
__device__ __forceinline__ void cp_async16(uint32_t dst, const void* src) {
    asm volatile("cp.async.cg.shared.global [%0], [%1], 16;\n"
                 :: "r"(dst), "l"(src) : "memory");
}
__device__ __forceinline__ void cp_async16p(uint32_t dst, const void* src, bool pred) {
    int sz = pred ? 16 : 0;
    asm volatile("cp.async.cg.shared.global [%0], [%1], 16, %2;\n"
                 :: "r"(dst), "l"(src), "r"(sz) : "memory");
}
__device__ __forceinline__ void cp_commit() {
    asm volatile("cp.async.commit_group;\n" ::: "memory");
}
__device__ __forceinline__ void cp_wait1() {
    asm volatile("cp.async.wait_group 1;\n" ::: "memory");
}
__device__ __forceinline__ uint32_t pack_bf16(float lo, float hi) {
    uint32_t r;
    asm("cvt.rn.bf16x2.f32 %0, %1, %2;" : "=r"(r) : "f"(hi), "f"(lo));
    return r;
}
__device__ __forceinline__ uint4 cvt_f4x2(float4 a, float4 b) {
    uint4 u;
    u.x = pack_bf16(a.x, a.y); u.y = pack_bf16(a.z, a.w);
    u.z = pack_bf16(b.x, b.y); u.w = pack_bf16(b.z, b.w);
    return u;
}
__device__ __forceinline__ void ldsm4(uint32_t& r0, uint32_t& r1, uint32_t& r2, uint32_t& r3,
                                      uint32_t addr) {
    asm volatile("ldmatrix.sync.aligned.m8n8.x4.shared.b16 {%0,%1,%2,%3}, [%4];"
                 : "=r"(r0), "=r"(r1), "=r"(r2), "=r"(r3) : "r"(addr));
}
__device__ __forceinline__ void ldsm4t(uint32_t& r0, uint32_t& r1, uint32_t& r2, uint32_t& r3,
                                       uint32_t addr) {
    asm volatile("ldmatrix.sync.aligned.m8n8.x4.trans.shared.b16 {%0,%1,%2,%3}, [%4];"
                 : "=r"(r0), "=r"(r1), "=r"(r2), "=r"(r3) : "r"(addr));
}
__device__ __forceinline__ void mma_bf16(float& c0, float& c1, float& c2, float& c3,
                                         uint32_t a0, uint32_t a1, uint32_t a2, uint32_t a3,
                                         uint32_t b0, uint32_t b1) {
    asm volatile(
        "mma.sync.aligned.m16n8k16.row.col.f32.bf16.bf16.f32 "
        "{%0,%1,%2,%3}, {%4,%5,%6,%7}, {%8,%9}, {%0,%1,%2,%3};\n"
        : "+f"(c0), "+f"(c1), "+f"(c2), "+f"(c3)
        : "r"(a0), "r"(a1), "r"(a2), "r"(a3), "r"(b0), "r"(b1));
}

// warp-tile compute: 32(M) x 64(N) x 32(K); 8 warps = 4x2 over 128x128
__device__ __forceinline__ void compute_tile(uint32_t aSlot, uint32_t bSlot,
                                             int lane, int wm, int wn,
                                             float c[2][8][4]) {
#pragma unroll
    for (int ks = 0; ks < 2; ++ks) {
        uint32_t a[2][4];
#pragma unroll
        for (int mi = 0; mi < 2; mi++) {
            uint32_t addr = aSlot + 2u * ((wm * 32 + mi * 16 + (lane & 15)) * AST
                                          + ks * 16 + (lane >> 4) * 8);
            ldsm4(a[mi][0], a[mi][1], a[mi][2], a[mi][3], addr);
        }
        uint32_t b[8][2];
#pragma unroll
        for (int nb = 0; nb < 4; nb++) {
            uint32_t addr = bSlot + 2u * ((ks * 16 + ((lane >> 3) & 1) * 8 + (lane & 7)) * BST
                                          + wn * 64 + nb * 16 + (lane >> 4) * 8);
            ldsm4t(b[2 * nb][0], b[2 * nb][1], b[2 * nb + 1][0], b[2 * nb + 1][1], addr);
        }
#pragma unroll
        for (int mi = 0; mi < 2; mi++)
#pragma unroll
            for (int ni = 0; ni < 8; ni++)
                mma_bf16(c[mi][ni][0], c[mi][ni][1], c[mi][ni][2], c[mi][ni][3],
                         a[mi][0], a[mi][1], a[mi][2], a[mi][3],
                         b[ni][0], b[ni][1]);
    }
}

// B-stage convert, SELF-MAPPED: each thread converts exactly the 4x16B chunks
// it cp.async'd itself (same geometry as the fill), so its own wait_group is
// sufficient ordering — no cross-thread visibility needed.
__device__ __forceinline__ void convert_B(char* smem, int tid, int f32slot, int b16slot) {
#pragma unroll
    for (int i = 0; i < 4; i++) {
        int f = tid + i * 256;
        int kr = f >> 5, seg = (f & 31) * 4;
        float4 v = *(const float4*)(smem + BF32_OFF + (size_t)f32slot * BF32_STAGE
                                    + ((size_t)kr * 128 + seg) * 4);
        *(uint2*)(smem + BB16_OFF + (size_t)b16slot * BB16_STAGE
                  + ((size_t)kr * BST + seg) * 2) =
            make_uint2(pack_bf16(v.x, v.y), pack_bf16(v.z, v.w));
    }
}

// ---------------- phase A0: x -> bf16 ----------------
__global__ void __launch_bounds__(256) xconv_kernel(const float* __restrict__ x) {
    const size_t base = ((size_t)blockIdx.x * 256 + threadIdx.x) * 16;
    const float4* s = (const float4*)(x + base);
    uint4* d = (uint4*)(g_xs + base);
    float4 v0 = s[0], v1 = s[1], v2 = s[2], v3 = s[3];
    d[0] = cvt_f4x2(v0, v1);
    d[1] = cvt_f4x2(v2, v3);
}

// ---------------- phase A: counting sort + worklist ----------------
__global__ void prep_kernel(const int* __restrict__ task_id, int B) {
    __shared__ int cnt[NT];
    __shared__ int off[NT + 1];
    __shared__ int cur[NT];
    int tid = threadIdx.x;
    if (tid < NT) cnt[tid] = 0;
    __syncthreads();
    for (int i = tid; i < B; i += blockDim.x)
        atomicAdd(&cnt[task_id[i]], 1);
    __syncthreads();
    if (tid == 0) {
        int s = 0, nw = 0;
        for (int t = 0; t < NT; t++) {
            off[t] = s;
            for (int m = s; m < s + cnt[t]; m += MTILE) {
                g_work_t[nw] = t; g_work_m0[nw] = m; nw++;
            }
            s += cnt[t];
        }
        off[NT] = s;
        g_nwork = nw;
    }
    __syncthreads();
    if (tid <= NT) g_offsets[tid] = off[tid];
    if (tid < NT)  cur[tid] = off[tid];
    __syncthreads();
    for (int i = tid; i < B; i += blockDim.x) {
        int t = task_id[i];
        int p = atomicAdd(&cur[t], 1);
        g_sorted[p]  = i;
        g_rowtask[p] = t;
    }
}

// ---------------- phase B: down-proj split-K ----------------
__global__ void __launch_bounds__(256, 2) down_kernel(const float* __restrict__ Wd) {
    if ((int)blockIdx.y >= g_nwork) return;
    const int t    = g_work_t[blockIdx.y];
    const int m0   = g_work_m0[blockIdx.y];
    const int rows = min(MTILE, g_offsets[t + 1] - m0);
    const int nb   = blockIdx.x & 1;
    const int kc   = blockIdx.x >> 1;
    const int n0   = nb * 128;
    const int ks0  = kc * KCHUNK;

    extern __shared__ __align__(16) char smem[];
    __shared__ int s_idx[MTILE];

    const int tid = threadIdx.x;
    if (tid < MTILE) s_idx[tid] = (tid < rows) ? g_sorted[m0 + tid] : -1;
    __syncthreads();

    const uint32_t sU = smem_u32(smem);
    const float* wsrc = Wd + (size_t)t * SIZE * NDOWN + n0;

    auto fill = [&](int j) {
        const int k0 = ks0 + j * KTILE;
        const uint32_t aS = sU + (uint32_t)(j % 3) * A_STAGE;
#pragma unroll
        for (int i = 0; i < 2; i++) {
            int f = tid + i * 256;
            int r = f >> 2, seg = (f & 3) * 8;
            int idx = s_idx[r];
            cp_async16p(aS + 2u * ((uint32_t)r * AST + seg),
                        g_xs + (size_t)(idx < 0 ? 0 : idx) * SIZE + k0 + seg, idx >= 0);
        }
        const uint32_t bS = sU + BF32_OFF + (uint32_t)(j % 3) * BF32_STAGE;
#pragma unroll
        for (int i = 0; i < 4; i++) {
            int f = tid + i * 256;
            int kr = f >> 5, seg = (f & 31) * 4;
            cp_async16(bS + 4u * ((uint32_t)kr * 128 + seg),
                       wsrc + (size_t)(k0 + kr) * NDOWN + seg);
        }
        cp_commit();
    };

    float c[2][8][4] = {};
    const int lane = tid & 31, wid = tid >> 5;
    const int wm = wid >> 1, wn = wid & 1;

    const int NIT = KCHUNK / KTILE;   // 16
    fill(0); fill(1);
    cp_wait1();
    convert_B(smem, tid, 0, 0);

    for (int j = 0; j < NIT; ++j) {
        __syncthreads();
        if (j + 2 < NIT) fill(j + 2);
        else             cp_commit();
        cp_wait1();
        if (j + 1 < NIT) convert_B(smem, tid, (j + 1) % 3, (j + 1) % 3);
        compute_tile(sU + (uint32_t)(j % 3) * A_STAGE,
                     sU + BB16_OFF + (uint32_t)(j % 3) * BB16_STAGE,
                     lane, wm, wn, c);
    }

    // write split-K partials
    const int g = lane >> 2, tg = lane & 3;
    float* pbase = &g_part[kc][0][0];
#pragma unroll
    for (int mi = 0; mi < 2; mi++) {
        int r0 = wm * 32 + mi * 16 + g;
        int r1 = r0 + 8;
#pragma unroll
        for (int ni = 0; ni < 8; ni++) {
            int col = wn * 64 + ni * 8 + tg * 2;
            if (r0 < rows)
                *(float2*)(pbase + (size_t)(m0 + r0) * NDOWN + n0 + col) =
                    make_float2(c[mi][ni][0], c[mi][ni][1]);
            if (r1 < rows)
                *(float2*)(pbase + (size_t)(m0 + r1) * NDOWN + n0 + col) =
                    make_float2(c[mi][ni][2], c[mi][ni][3]);
        }
    }
}

// ---------------- phase B2: reduce partials + bias + silu -> bf16 ------------
__global__ void __launch_bounds__(1024) reduce_kernel(const float* __restrict__ bd, int B) {
    int gidx = blockIdx.x * 1024 + threadIdx.x;
    if (gidx >= B * NDOWN) return;
    int pos = gidx >> 8;
    int col = gidx & (NDOWN - 1);
    float s = 0.f;
#pragma unroll
    for (int k = 0; k < KSPLIT; k++)
        s += g_part[k][pos][col];
    s += bd[g_rowtask[pos] * NDOWN + col];
    g_act[gidx] = __float2bfloat16(s / (1.f + __expf(-s)));
}

// ---------------- phase C: up-proj + bias + residual -------------------------
__global__ void __launch_bounds__(256, 2) up_kernel(const float* __restrict__ x,
                                                    const float* __restrict__ Wu,
                                                    const float* __restrict__ bu,
                                                    float* __restrict__ out) {
    if ((int)blockIdx.y >= g_nwork) return;
    const int t    = g_work_t[blockIdx.y];
    const int m0   = g_work_m0[blockIdx.y];
    const int rows = min(MTILE, g_offsets[t + 1] - m0);
    const int n0   = blockIdx.x * 128;

    extern __shared__ __align__(16) char smem[];
    __shared__ int s_orig[MTILE];

    const int tid = threadIdx.x;
    if (tid < MTILE) s_orig[tid] = (tid < rows) ? g_sorted[m0 + tid] : 0;
    __syncthreads();

    const uint32_t sU = smem_u32(smem);
    const __nv_bfloat16* asrc = g_act + (size_t)m0 * NDOWN;
    const float*         wsrc = Wu + (size_t)t * NDOWN * SIZE + n0;

    auto fill = [&](int j) {
        const int k0 = j * KTILE;
        const uint32_t aS = sU + (uint32_t)(j % 3) * A_STAGE;
#pragma unroll
        for (int i = 0; i < 2; i++) {
            int f = tid + i * 256;
            int r = f >> 2, seg = (f & 3) * 8;
            cp_async16(aS + 2u * ((uint32_t)r * AST + seg),
                       asrc + (size_t)r * NDOWN + k0 + seg);
        }
        const uint32_t bS = sU + BF32_OFF + (uint32_t)(j % 3) * BF32_STAGE;
#pragma unroll
        for (int i = 0; i < 4; i++) {
            int f = tid + i * 256;
            int kr = f >> 5, seg = (f & 31) * 4;
            cp_async16(bS + 4u * ((uint32_t)kr * 128 + seg),
                       wsrc + (size_t)(k0 + kr) * SIZE + seg);
        }
        cp_commit();
    };

    float c[2][8][4] = {};
    const int lane = tid & 31, wid = tid >> 5;
    const int wm = wid >> 1, wn = wid & 1;

    const int NIT = NDOWN / KTILE;   // 8
    fill(0); fill(1);
    cp_wait1();
    convert_B(smem, tid, 0, 0);

    for (int j = 0; j < NIT; ++j) {
        __syncthreads();
        if (j + 2 < NIT) fill(j + 2);
        else             cp_commit();
        cp_wait1();
        if (j + 1 < NIT) convert_B(smem, tid, (j + 1) % 3, (j + 1) % 3);
        compute_tile(sU + (uint32_t)(j % 3) * A_STAGE,
                     sU + BB16_OFF + (uint32_t)(j % 3) * BB16_STAGE,
                     lane, wm, wn, c);
    }

    // epilogue: out[orig] = x[orig] + acc + bu[t]
    const int g = lane >> 2, tg = lane & 3;
    const float* bup = bu + (size_t)t * SIZE + n0;
#pragma unroll
    for (int mi = 0; mi < 2; mi++) {
        int r0 = wm * 32 + mi * 16 + g;
        int r1 = r0 + 8;
#pragma unroll
        for (int ni = 0; ni < 8; ni++) {
            int col = wn * 64 + ni * 8 + tg * 2;
            float b0 = bup[col], b1 = bup[col + 1];
            if (r0 < rows) {
                size_t o = (size_t)s_orig[r0] * SIZE + n0 + col;
                out[o]     = x[o]     + c[mi][ni][0] + b0;
                out[o + 1] = x[o + 1] + c[mi][ni][1] + b1;
            }
            if (r1 < rows) {
                size_t o = (size_t)s_orig[r1] * SIZE + n0 + col;
                out[o]     = x[o]     + c[mi][ni][2] + b0;
                out[o + 1] = x[o + 1] + c[mi][ni][3] + b1;
            }
        }
    }
}

// ---------------- launch ----------------
extern "C" void kernel_launch(void* const* d_in, const int* in_sizes, int n_in,
                              void* d_out, int out_size) {
    const float* x       = (const float*)d_in[0];
    const int*   task_id = (const int*)d_in[1];
    const float* Wd      = (const float*)d_in[2];
    const float* bd      = (const float*)d_in[3];
    const float* Wu      = (const float*)d_in[4];
    const float* bu      = (const float*)d_in[5];
    float*       out     = (float*)d_out;
    const int B = in_sizes[1];

    xconv_kernel<<<B, 256>>>(x);
    prep_kernel<<<1, 1024>>>(task_id, B);

    cudaFuncSetAttribute(down_kernel, cudaFuncAttributeMaxDynamicSharedMemorySize, SMEM_DYN);
    cudaFuncSetAttribute(up_kernel,   cudaFuncAttributeMaxDynamicSharedMemorySize, SMEM_DYN);

    const int maxWork = B / MTILE + NT;
    dim3 gD(2 * KSPLIT, maxWork);
    down_kernel<<<gD, 256, SMEM_DYN>>>(Wd);

    reduce_kernel<<<(B * NDOWN + 1023) / 1024, 1024>>>(bd, B);

    dim3 gU(SIZE / 128, maxWork);
    up_kernel<<<gU, 256, SMEM_DYN>>>(x, Wu, bu, out);
}

// round 8
// speedup vs baseline: 1.4128x; 1.0442x over previous
#include <cuda_runtime.h>
#include <cuda_bf16.h>
#include <cstdint>

#define SIZE   4096
#define NDOWN  256
#define NT     16
#define MAXB   4096
#define MTILE  128
#define KSPLIT 8
#define KCHUNK (SIZE / KSPLIT)   // 512
#define KTILE  32

#define AST 40    // A smem stride (bf16): 80B rows, ldmatrix conflict-free
#define BST 136   // B smem stride (bf16): 272B rows, ldmatrix.trans conflict-free

// smem layout (per CTA)
#define A_STAGE   (MTILE * AST * 2)             // 10240
#define BF32_OFF  (3 * A_STAGE)                 // 30720
#define BF32_STAGE (KTILE * 128 * 4)            // 16384
#define BB16_OFF  (BF32_OFF + 3 * BF32_STAGE)   // 79872
#define BB16_STAGE (KTILE * BST * 2)            // 8704
#define SMEM_DYN  (BB16_OFF + 3 * BB16_STAGE)   // 105984

// ---------------- device scratch ----------------
__device__ int   g_offsets[NT + 1];
__device__ int   g_sorted[MAXB];
__device__ int   g_rowtask[MAXB];
__device__ int   g_work_t[MAXB / MTILE + NT];
__device__ int   g_work_m0[MAXB / MTILE + NT];
__device__ int   g_nwork;
__device__ __align__(16) __nv_bfloat16 g_part[KSPLIT][MAXB][NDOWN];   // bf16 partials (16.5MB)
__device__ __align__(16) __nv_bfloat16 g_act[(size_t)MAXB * NDOWN];
__device__ __align__(16) __nv_bfloat16 g_xs[(size_t)MAXB * SIZE];     // bf16 copy of x

// ---------------- helpers ----------------
__device__ __forceinline__ uint32_t smem_u32(const void* p) {
    return (uint32_t)__cvta_generic_to_shared(p);
}
__device__ __forceinline__ void cp_async16(uint32_t dst, const void* src) {
    asm volatile("cp.async.cg.shared.global [%0], [%1], 16;\n"
                 :: "r"(dst), "l"(src) : "memory");
}
__device__ __forceinline__ void cp_async16p(uint32_t dst, const void* src, bool pred) {
    int sz = pred ? 16 : 0;
    asm volatile("cp.async.cg.shared.global [%0], [%1], 16, %2;\n"
                 :: "r"(dst), "l"(src), "r"(sz) : "memory");
}
__device__ __forceinline__ void cp_commit() {
    asm volatile("cp.async.commit_group;\n" ::: "memory");
}
__device__ __forceinline__ void cp_wait1() {
    asm volatile("cp.async.wait_group 1;\n" ::: "memory");
}
__device__ __forceinline__ uint32_t pack_bf16(float lo, float hi) {
    uint32_t r;
    asm("cvt.rn.bf16x2.f32 %0, %1, %2;" : "=r"(r) : "f"(hi), "f"(lo));
    return r;
}
__device__ __forceinline__ uint4 cvt_f4x2(float4 a, float4 b) {
    uint4 u;
    u.x = pack_bf16(a.x, a.y); u.y = pack_bf16(a.z, a.w);
    u.z = pack_bf16(b.x, b.y); u.w = pack_bf16(b.z, b.w);
    return u;
}
__device__ __forceinline__ void ldsm4(uint32_t& r0, uint32_t& r1, uint32_t& r2, uint32_t& r3,
                                      uint32_t addr) {
    asm volatile("ldmatrix.sync.aligned.m8n8.x4.shared.b16 {%0,%1,%2,%3}, [%4];"
                 : "=r"(r0), "=r"(r1), "=r"(r2), "=r"(r3) : "r"(addr));
}
__device__ __forceinline__ void ldsm4t(uint32_t& r0, uint32_t& r1, uint32_t& r2, uint32_t& r3,
                                       uint32_t addr) {
    asm volatile("ldmatrix.sync.aligned.m8n8.x4.trans.shared.b16 {%0,%1,%2,%3}, [%4];"
                 : "=r"(r0), "=r"(r1), "=r"(r2), "=r"(r3) : "r"(addr));
}
__device__ __forceinline__ void mma_bf16(float& c0, float& c1, float& c2, float& c3,
                                         uint32_t a0, uint32_t a1, uint32_t a2, uint32_t a3,
                                         uint32_t b0, uint32_t b1) {
    asm volatile(
        "mma.sync.aligned.m16n8k16.row.col.f32.bf16.bf16.f32 "
        "{%0,%1,%2,%3}, {%4,%5,%6,%7}, {%8,%9}, {%0,%1,%2,%3};\n"
        : "+f"(c0), "+f"(c1), "+f"(c2), "+f"(c3)
        : "r"(a0), "r"(a1), "r"(a2), "r"(a3), "r"(b0), "r"(b1));
}

// warp-tile compute: 32(M) x 64(N) x 32(K); 8 warps = 4x2 over 128x128
__device__ __forceinline__ void compute_tile(uint32_t aSlot, uint32_t bSlot,
                                             int lane, int wm, int wn,
                                             float c[2][8][4]) {
#pragma unroll
    for (int ks = 0; ks < 2; ++ks) {
        uint32_t a[2][4];
#pragma unroll
        for (int mi = 0; mi < 2; mi++) {
            uint32_t addr = aSlot + 2u * ((wm * 32 + mi * 16 + (lane & 15)) * AST
                                          + ks * 16 + (lane >> 4) * 8);
            ldsm4(a[mi][0], a[mi][1], a[mi][2], a[mi][3], addr);
        }
        uint32_t b[8][2];
#pragma unroll
        for (int nb = 0; nb < 4; nb++) {
            uint32_t addr = bSlot + 2u * ((ks * 16 + ((lane >> 3) & 1) * 8 + (lane & 7)) * BST
                                          + wn * 64 + nb * 16 + (lane >> 4) * 8);
            ldsm4t(b[2 * nb][0], b[2 * nb][1], b[2 * nb + 1][0], b[2 * nb + 1][1], addr);
        }
#pragma unroll
        for (int mi = 0; mi < 2; mi++)
#pragma unroll
            for (int ni = 0; ni < 8; ni++)
                mma_bf16(c[mi][ni][0], c[mi][ni][1], c[mi][ni][2], c[mi][ni][3],
                         a[mi][0], a[mi][1], a[mi][2], a[mi][3],
                         b[ni][0], b[ni][1]);
    }
}

// B-stage convert, SELF-MAPPED (each thread converts the chunks it cp.async'd)
__device__ __forceinline__ void convert_B(char* smem, int tid, int f32slot, int b16slot) {
#pragma unroll
    for (int i = 0; i < 4; i++) {
        int f = tid + i * 256;
        int kr = f >> 5, seg = (f & 31) * 4;
        float4 v = *(const float4*)(smem + BF32_OFF + (size_t)f32slot * BF32_STAGE
                                    + ((size_t)kr * 128 + seg) * 4);
        *(uint2*)(smem + BB16_OFF + (size_t)b16slot * BB16_STAGE
                  + ((size_t)kr * BST + seg) * 2) =
            make_uint2(pack_bf16(v.x, v.y), pack_bf16(v.z, v.w));
    }
}

// ------------- phase A: fused x->bf16 conversion + counting sort -------------
__global__ void __launch_bounds__(256) xconv_prep_kernel(const float* __restrict__ x,
                                                         const int* __restrict__ task_id,
                                                         int B) {
    if ((int)blockIdx.x < B) {
        const size_t base = ((size_t)blockIdx.x * 256 + threadIdx.x) * 16;
        const float4* s = (const float4*)(x + base);
        uint4* d = (uint4*)(g_xs + base);
        float4 v0 = s[0], v1 = s[1], v2 = s[2], v3 = s[3];
        d[0] = cvt_f4x2(v0, v1);
        d[1] = cvt_f4x2(v2, v3);
        return;
    }
    // last block: counting sort + worklist
    __shared__ int cnt[NT];
    __shared__ int off[NT + 1];
    __shared__ int cur[NT];
    int tid = threadIdx.x;
    if (tid < NT) cnt[tid] = 0;
    __syncthreads();
    for (int i = tid; i < B; i += blockDim.x)
        atomicAdd(&cnt[task_id[i]], 1);
    __syncthreads();
    if (tid == 0) {
        int s = 0, nw = 0;
        for (int t = 0; t < NT; t++) {
            off[t] = s;
            for (int m = s; m < s + cnt[t]; m += MTILE) {
                g_work_t[nw] = t; g_work_m0[nw] = m; nw++;
            }
            s += cnt[t];
        }
        off[NT] = s;
        g_nwork = nw;
    }
    __syncthreads();
    if (tid <= NT) g_offsets[tid] = off[tid];
    if (tid < NT)  cur[tid] = off[tid];
    __syncthreads();
    for (int i = tid; i < B; i += blockDim.x) {
        int t = task_id[i];
        int p = atomicAdd(&cur[t], 1);
        g_sorted[p]  = i;
        g_rowtask[p] = t;
    }
}

// ---------------- phase B: down-proj split-K ----------------
__global__ void __launch_bounds__(256, 2) down_kernel(const float* __restrict__ Wd) {
    if ((int)blockIdx.y >= g_nwork) return;
    const int t    = g_work_t[blockIdx.y];
    const int m0   = g_work_m0[blockIdx.y];
    const int rows = min(MTILE, g_offsets[t + 1] - m0);
    const int nb   = blockIdx.x & 1;
    const int kc   = blockIdx.x >> 1;
    const int n0   = nb * 128;
    const int ks0  = kc * KCHUNK;

    extern __shared__ __align__(16) char smem[];
    __shared__ int s_idx[MTILE];

    const int tid = threadIdx.x;
    if (tid < MTILE) s_idx[tid] = (tid < rows) ? g_sorted[m0 + tid] : -1;
    __syncthreads();

    const uint32_t sU = smem_u32(smem);
    const float* wsrc = Wd + (size_t)t * SIZE * NDOWN + n0;

    auto fill = [&](int j) {
        const int k0 = ks0 + j * KTILE;
        const uint32_t aS = sU + (uint32_t)(j % 3) * A_STAGE;
#pragma unroll
        for (int i = 0; i < 2; i++) {
            int f = tid + i * 256;
            int r = f >> 2, seg = (f & 3) * 8;
            int idx = s_idx[r];
            cp_async16p(aS + 2u * ((uint32_t)r * AST + seg),
                        g_xs + (size_t)(idx < 0 ? 0 : idx) * SIZE + k0 + seg, idx >= 0);
        }
        const uint32_t bS = sU + BF32_OFF + (uint32_t)(j % 3) * BF32_STAGE;
#pragma unroll
        for (int i = 0; i < 4; i++) {
            int f = tid + i * 256;
            int kr = f >> 5, seg = (f & 31) * 4;
            cp_async16(bS + 4u * ((uint32_t)kr * 128 + seg),
                       wsrc + (size_t)(k0 + kr) * NDOWN + seg);
        }
        cp_commit();
    };

    float c[2][8][4] = {};
    const int lane = tid & 31, wid = tid >> 5;
    const int wm = wid >> 1, wn = wid & 1;

    const int NIT = KCHUNK / KTILE;   // 16
    fill(0); fill(1);
    cp_wait1();
    convert_B(smem, tid, 0, 0);

#pragma unroll
    for (int j = 0; j < NIT; ++j) {
        __syncthreads();
        if (j + 2 < NIT) fill(j + 2);
        else             cp_commit();
        cp_wait1();
        if (j + 1 < NIT) convert_B(smem, tid, (j + 1) % 3, (j + 1) % 3);
        compute_tile(sU + (uint32_t)(j % 3) * A_STAGE,
                     sU + BB16_OFF + (uint32_t)(j % 3) * BB16_STAGE,
                     lane, wm, wn, c);
    }

    // write split-K partials (packed bf16x2)
    const int g = lane >> 2, tg = lane & 3;
    __nv_bfloat16* pbase = &g_part[kc][0][0];
#pragma unroll
    for (int mi = 0; mi < 2; mi++) {
        int r0 = wm * 32 + mi * 16 + g;
        int r1 = r0 + 8;
#pragma unroll
        for (int ni = 0; ni < 8; ni++) {
            int col = wn * 64 + ni * 8 + tg * 2;
            if (r0 < rows)
                *(uint32_t*)(pbase + (size_t)(m0 + r0) * NDOWN + n0 + col) =
                    pack_bf16(c[mi][ni][0], c[mi][ni][1]);
            if (r1 < rows)
                *(uint32_t*)(pbase + (size_t)(m0 + r1) * NDOWN + n0 + col) =
                    pack_bf16(c[mi][ni][2], c[mi][ni][3]);
        }
    }
}

// ---------------- phase B2: reduce bf16 partials + bias + silu ---------------
// one thread = 8 consecutive cols of one row; uint4 loads (8 bf16)
__global__ void __launch_bounds__(1024) reduce_kernel(const float* __restrict__ bd, int B) {
    int gidx = blockIdx.x * 1024 + threadIdx.x;
    if (gidx >= B * (NDOWN / 8)) return;
    int pos  = gidx >> 5;
    int col8 = (gidx & 31) * 8;

    float s[8] = {};
#pragma unroll
    for (int k = 0; k < KSPLIT; k++) {
        uint4 v = *(const uint4*)(&g_part[k][pos][col8]);
        const uint32_t w[4] = {v.x, v.y, v.z, v.w};
#pragma unroll
        for (int q = 0; q < 4; q++) {
            __nv_bfloat162 p = *(const __nv_bfloat162*)&w[q];
            s[2 * q]     += __bfloat162float(p.x);
            s[2 * q + 1] += __bfloat162float(p.y);
        }
    }
    const float* bp = bd + g_rowtask[pos] * NDOWN + col8;
    uint32_t o[4];
#pragma unroll
    for (int q = 0; q < 4; q++) {
        float a0 = s[2 * q] + bp[2 * q];
        float a1 = s[2 * q + 1] + bp[2 * q + 1];
        a0 = a0 / (1.f + __expf(-a0));
        a1 = a1 / (1.f + __expf(-a1));
        o[q] = pack_bf16(a0, a1);
    }
    *(uint4*)(g_act + (size_t)pos * NDOWN + col8) = make_uint4(o[0], o[1], o[2], o[3]);
}

// ---------------- phase C: up-proj + bias + residual -------------------------
__global__ void __launch_bounds__(256, 2) up_kernel(const float* __restrict__ x,
                                                    const float* __restrict__ Wu,
                                                    const float* __restrict__ bu,
                                                    float* __restrict__ out) {
    if ((int)blockIdx.y >= g_nwork) return;
    const int t    = g_work_t[blockIdx.y];
    const int m0   = g_work_m0[blockIdx.y];
    const int rows = min(MTILE, g_offsets[t + 1] - m0);
    const int n0   = blockIdx.x * 128;

    extern __shared__ __align__(16) char smem[];
    __shared__ int s_orig[MTILE];

    const int tid = threadIdx.x;
    if (tid < MTILE) s_orig[tid] = (tid < rows) ? g_sorted[m0 + tid] : 0;
    __syncthreads();

    const uint32_t sU = smem_u32(smem);
    const __nv_bfloat16* asrc = g_act + (size_t)m0 * NDOWN;
    const float*         wsrc = Wu + (size_t)t * NDOWN * SIZE + n0;

    auto fill = [&](int j) {
        const int k0 = j * KTILE;
        const uint32_t aS = sU + (uint32_t)(j % 3) * A_STAGE;
#pragma unroll
        for (int i = 0; i < 2; i++) {
            int f = tid + i * 256;
            int r = f >> 2, seg = (f & 3) * 8;
            cp_async16(aS + 2u * ((uint32_t)r * AST + seg),
                       asrc + (size_t)r * NDOWN + k0 + seg);
        }
        const uint32_t bS = sU + BF32_OFF + (uint32_t)(j % 3) * BF32_STAGE;
#pragma unroll
        for (int i = 0; i < 4; i++) {
            int f = tid + i * 256;
            int kr = f >> 5, seg = (f & 31) * 4;
            cp_async16(bS + 4u * ((uint32_t)kr * 128 + seg),
                       wsrc + (size_t)(k0 + kr) * SIZE + seg);
        }
        cp_commit();
    };

    float c[2][8][4] = {};
    const int lane = tid & 31, wid = tid >> 5;
    const int wm = wid >> 1, wn = wid & 1;

    const int NIT = NDOWN / KTILE;   // 8
    fill(0); fill(1);
    cp_wait1();
    convert_B(smem, tid, 0, 0);

#pragma unroll
    for (int j = 0; j < NIT; ++j) {
        __syncthreads();
        if (j + 2 < NIT) fill(j + 2);
        else             cp_commit();
        cp_wait1();
        if (j + 1 < NIT) convert_B(smem, tid, (j + 1) % 3, (j + 1) % 3);
        compute_tile(sU + (uint32_t)(j % 3) * A_STAGE,
                     sU + BB16_OFF + (uint32_t)(j % 3) * BB16_STAGE,
                     lane, wm, wn, c);
    }

    // epilogue: out[orig] = x[orig] + acc + bu[t]
    const int g = lane >> 2, tg = lane & 3;
    const float* bup = bu + (size_t)t * SIZE + n0;
#pragma unroll
    for (int mi = 0; mi < 2; mi++) {
        int r0 = wm * 32 + mi * 16 + g;
        int r1 = r0 + 8;
#pragma unroll
        for (int ni = 0; ni < 8; ni++) {
            int col = wn * 64 + ni * 8 + tg * 2;
            float b0 = bup[col], b1 = bup[col + 1];
            if (r0 < rows) {
                size_t o = (size_t)s_orig[r0] * SIZE + n0 + col;
                out[o]     = x[o]     + c[mi][ni][0] + b0;
                out[o + 1] = x[o + 1] + c[mi][ni][1] + b1;
            }
            if (r1 < rows) {
                size_t o = (size_t)s_orig[r1] * SIZE + n0 + col;
                out[o]     = x[o]     + c[mi][ni][2] + b0;
                out[o + 1] = x[o + 1] + c[mi][ni][3] + b1;
            }
        }
    }
}

// ---------------- launch ----------------
extern "C" void kernel_launch(void* const* d_in, const int* in_sizes, int n_in,
                              void* d_out, int out_size) {
    const float* x       = (const float*)d_in[0];
    const int*   task_id = (const int*)d_in[1];
    const float* Wd      = (const float*)d_in[2];
    const float* bd      = (const float*)d_in[3];
    const float* Wu      = (const float*)d_in[4];
    const float* bu      = (const float*)d_in[5];
    float*       out     = (float*)d_out;
    const int B = in_sizes[1];

    xconv_prep_kernel<<<B + 1, 256>>>(x, task_id, B);

    cudaFuncSetAttribute(down_kernel, cudaFuncAttributeMaxDynamicSharedMemorySize, SMEM_DYN);
    cudaFuncSetAttribute(up_kernel,   cudaFuncAttributeMaxDynamicSharedMemorySize, SMEM_DYN);

    const int maxWork = B / MTILE + NT;
    dim3 gD(2 * KSPLIT, maxWork);
    down_kernel<<<gD, 256, SMEM_DYN>>>(Wd);

    reduce_kernel<<<(B * (NDOWN / 8) + 1023) / 1024, 1024>>>(bd, B);

    dim3 gU(SIZE / 128, maxWork);
    up_kernel<<<gU, 256, SMEM_DYN>>>(x, Wu, bu, out);
}